// round 16
// baseline (speedup 1.0000x reference)
#include <cuda_runtime.h>
#include <cuda_bf16.h>
#include <cstdint>

// Problem constants
#define BB 16
#define PP 16
#define CC 1024
#define DD 128

// ---------------------------------------------------------------------------
// Single fused kernel, cluster-scoped softmax.
//   grid = 128 CTAs x 1024 threads, cluster = 8 CTAs; one cluster == one
//   batch b (8 x 2048 candidates = 16384 = P*C). Each warp owns 64
//   consecutive candidates (all within one (b,p)).
//   e = exp(dot128(cand_emb, score_w[384:512])) for c < cand_len, else 0.
//   (query/v1/v2 score terms are constant per-b and cancel in the softmax;
//    max-shift unnecessary, |logit| <~ 1.5.)
//   MLP = 8 loads in flight per warp: at 1 CTA/SM (reg-limited) this restores
//   the 256 LDG.128/SM in-flight depth that the 8-CTA/SM R10 config had
//   (R15's MLP=4 at 32 warps/SM was latency-starved: DRAM 22%).
//   Butterfly reduce leaves dots in ALL lanes -> lane l keeps candidates
//   2l,2l+1 in registers; output written ONCE, already normalized.
//   Denominator exchanged across the cluster via DSMEM (CTA/cluster scope
//   only -- no gpu-scope fences, no atomics, no second launch).
// ---------------------------------------------------------------------------
__global__ __launch_bounds__(1024, 1) void fused_cluster_kernel(
    const float* __restrict__ cand_emb,   // (B,P,C,D)
    const int*   __restrict__ cand_len,   // (B,P)
    const float* __restrict__ score_w,    // (1, 512)
    float*       __restrict__ out)        // (B, P*C) final softmax
{
    __shared__ float wsum[32];
    __shared__ float cSum;     // this CTA's partial sum (DSMEM-visible)
    __shared__ float sInv;

    const int tid  = threadIdx.x;
    const int lane = tid & 31;
    const int warp = tid >> 5;
    const int bid  = blockIdx.x;              // 0..127

    // CTA covers candidates [bid*2048, +2048) = 2 (b,p) pairs.
    const int bp   = bid * 2 + (warp >> 4);   // warps 0-15 -> bp0, 16-31 -> bp1
    const int clen = __ldg(&cand_len[bp]);

    // candidate-embedding slice of score_w: offset 3*128 = 384
    const float4 wv = reinterpret_cast<const float4*>(score_w + 3 * DD)[lane];

    // this warp's 64 candidates start at flat index bid*2048 + warp*64
    const float4* __restrict__ src =
        reinterpret_cast<const float4*>(cand_emb) +
        ((size_t)bid * 2048 + (size_t)warp * 64) * 32;   // 32 float4 / cand

    const int cBase = (warp & 15) * 64;       // within-(b,p) candidate base

    float eLo = 0.0f, eHi = 0.0f;             // kept: idx 2*lane, 2*lane+1
    float wsumLocal = 0.0f;                   // per-lane running sum of kept e

    #pragma unroll
    for (int i = 0; i < 8; i++) {
        const int j0 = i * 8;
        bool  v[8];
        float s[8];

        // 8 LDG.128 in flight (warp-uniform predicate: masked = no traffic)
        #pragma unroll
        for (int j = 0; j < 8; j++) {
            v[j] = (cBase + j0 + j) < clen;
            float4 a = v[j] ? src[(size_t)(j0 + j) * 32 + lane]
                            : make_float4(0.f, 0.f, 0.f, 0.f);
            s[j] = a.x * wv.x + a.y * wv.y + a.z * wv.z + a.w * wv.w;
        }

        #pragma unroll
        for (int o = 16; o > 0; o >>= 1) {
            #pragma unroll
            for (int j = 0; j < 8; j++)
                s[j] += __shfl_xor_sync(0xFFFFFFFFu, s[j], o);
        }

        // all lanes hold the 8 dots; exp (MUFU) then keep ours
        float e[8];
        #pragma unroll
        for (int j = 0; j < 8; j++)
            e[j] = v[j] ? __expf(s[j]) : 0.0f;

        // iteration i covers candidates 8i..8i+7 -> lanes 4i..4i+3.
        // lane l keeps candidates 2l, 2l+1: position k = lane&3 within iter,
        // eLo = e[2k], eHi = e[2k+1]  (2-level select tree, no local mem)
        if ((lane >> 2) == i) {
            const int k = lane & 3;
            eLo = (k < 2) ? ((k & 1) ? e[2] : e[0]) : ((k & 1) ? e[6] : e[4]);
            eHi = (k < 2) ? ((k & 1) ? e[3] : e[1]) : ((k & 1) ? e[7] : e[5]);
        }
        // every lane accumulates its share of the warp sum (lane-local; the
        // kept-pair trick means lane l's eLo/eHi cover all 64 once summed)
    }
    wsumLocal = eLo + eHi;

    // ---- warp sum of its 64 e-values (each lane holds exactly 2) ----
    float wl = wsumLocal;
    #pragma unroll
    for (int o = 16; o > 0; o >>= 1)
        wl += __shfl_xor_sync(0xFFFFFFFFu, wl, o);
    if (lane == 0) wsum[warp] = wl;
    __syncthreads();

    // ---- block sum -> cSum (cluster-visible smem) ----
    if (warp == 0) {
        float s = wsum[lane];
        #pragma unroll
        for (int o = 16; o > 0; o >>= 1)
            s += __shfl_xor_sync(0xFFFFFFFFu, s, o);
        if (lane == 0) cSum = s;
    }
    // cluster barrier publishes cSum across the 8 CTAs
    asm volatile("barrier.cluster.arrive.aligned;" ::: "memory");
    asm volatile("barrier.cluster.wait.aligned;"   ::: "memory");

    // ---- warp 0: gather the 8 per-CTA sums via DSMEM, broadcast 1/sum ----
    if (warp == 0) {
        uint32_t localAddr;
        asm("{ .reg .u64 t; cvta.to.shared.u64 t, %1; cvt.u32.u64 %0, t; }"
            : "=r"(localAddr) : "l"(&cSum));
        float ps = 0.0f;
        if (lane < 8) {
            uint32_t remAddr;
            asm("mapa.shared::cluster.u32 %0, %1, %2;"
                : "=r"(remAddr) : "r"(localAddr), "r"(lane));
            asm("ld.shared::cluster.f32 %0, [%1];"
                : "=f"(ps) : "r"(remAddr));
        }
        #pragma unroll
        for (int o = 4; o > 0; o >>= 1)
            ps += __shfl_xor_sync(0xFFFFFFFFu, ps, o);
        if (lane == 0) sInv = 1.0f / ps;
    }
    __syncthreads();
    const float inv = sInv;

    // ---- write this warp's 64 normalized values: one float2 per lane ----
    float2* __restrict__ dst =
        reinterpret_cast<float2*>(out) + (size_t)bid * 1024 + warp * 32 + lane;
    *dst = make_float2(eLo * inv, eHi * inv);

    // keep cluster smem alive until all peers finished their DSMEM reads
    asm volatile("barrier.cluster.arrive.aligned;" ::: "memory");
    asm volatile("barrier.cluster.wait.aligned;"   ::: "memory");
}

// ---------------------------------------------------------------------------
// Inputs (metadata order):
//  0 query  1 path_emb  2 path_len  3 cand_emb  4 cand_len  5..18 weights
// 19 score_w (1,512)   20 score_b
// Output: (B, P*C) float32 = 262144
// ---------------------------------------------------------------------------
extern "C" void kernel_launch(void* const* d_in, const int* in_sizes, int n_in,
                              void* d_out, int out_size) {
    const float* cand_emb = (const float*)d_in[3];
    const int*   cand_len = (const int*)d_in[4];
    const float* score_w  = (const float*)d_in[19];
    float* out = (float*)d_out;

    cudaLaunchConfig_t cfg = {};
    cfg.gridDim  = dim3(128);      // 16 clusters x 8 CTAs = 16 batches
    cfg.blockDim = dim3(1024);
    cfg.dynamicSmemBytes = 0;
    cfg.stream = 0;
    cudaLaunchAttribute attr[1];
    attr[0].id = cudaLaunchAttributeClusterDimension;
    attr[0].val.clusterDim = {8, 1, 1};
    cfg.attrs = attr;
    cfg.numAttrs = 1;
    cudaLaunchKernelEx(&cfg, fused_cluster_kernel, cand_emb, cand_len, score_w, out);
}